// round 16
// baseline (speedup 1.0000x reference)
#include <cuda_runtime.h>

#define BB 16
#define SS 4096
#define HH 16
#define EE 64
#define SDIM 64
#define NW 127

__device__ float g_vs2[2*BB*HH*SDIM*EE];
__device__ float g_us[BB*HH*SDIM*EE];

__global__ __launch_bounds__(256) void k_reduce(const float* __restrict__ v) {
    int bid = blockIdx.x;
    int bh = bid >> 1, half = bid & 1;
    int b = bh >> 4, h = bh & 15;
    int t = threadIdx.x;
    int e4 = t & 15, sub = (t >> 4) & 1, w = t >> 5;

    __shared__ float4 stage[2][8*8*16];

    const float4* v4 = reinterpret_cast<const float4*>(v)
                     + (size_t)b*SS*(HH*EE/4) + h*(EE/4) + e4;

    int i0 = half*32 + w*4 + sub*2;
    float4 crow0 = make_float4(0.f,0.f,0.f,0.f);
    float4 crow1 = make_float4(0.f,0.f,0.f,0.f);

    float* vs_dst = g_vs2 + (size_t)(half*BB*HH + bh)*SDIM*EE;

    #pragma unroll 1
    for (int jc = 0; jc < 8; ++jc) {
        float4 vloc[8];
        const float4* p0 = v4 + (size_t)(i0*SDIM + jc*8)*(HH*EE/4);
        const float4* p1 = p0 + (size_t)SDIM*(HH*EE/4);
        #pragma unroll
        for (int jj = 0; jj < 8; ++jj) {
            float4 a = __ldcs(p0 + (size_t)jj*(HH*EE/4));
            float4 c = __ldcs(p1 + (size_t)jj*(HH*EE/4));
            crow0.x += a.x; crow0.y += a.y; crow0.z += a.z; crow0.w += a.w;
            crow1.x += c.x; crow1.y += c.y; crow1.z += c.z; crow1.w += c.w;
            vloc[jj] = make_float4(a.x + c.x, a.y + c.y, a.z + c.z, a.w + c.w);
        }
        #pragma unroll
        for (int jj = 0; jj < 8; ++jj) {
            vloc[jj].x += __shfl_down_sync(0xffffffffu, vloc[jj].x, 16);
            vloc[jj].y += __shfl_down_sync(0xffffffffu, vloc[jj].y, 16);
            vloc[jj].z += __shfl_down_sync(0xffffffffu, vloc[jj].z, 16);
            vloc[jj].w += __shfl_down_sync(0xffffffffu, vloc[jj].w, 16);
        }
        if (sub == 0) {
            #pragma unroll
            for (int jj = 0; jj < 8; ++jj)
                stage[jc & 1][(w*8 + jj)*16 + e4] = vloc[jj];
        }
        __syncthreads();

        bool lower = (t < 128);
        if (lower == ((jc & 1) == 0)) {
            int tt = t & 127;
            int jj = tt >> 4, ee = tt & 15;
            float4 s = stage[jc & 1][jj*16 + ee];
            #pragma unroll
            for (int ww = 1; ww < 8; ++ww) {
                float4 x = stage[jc & 1][(ww*8 + jj)*16 + ee];
                s.x += x.x; s.y += x.y; s.z += x.z; s.w += x.w;
            }
            reinterpret_cast<float4*>(vs_dst + (jc*8 + jj)*EE)[ee] = s;
        }
    }

    float4* us4 = reinterpret_cast<float4*>(g_us + (size_t)bh*SDIM*EE);
    us4[(i0    )*(EE/4) + e4] = crow0;
    us4[(i0 + 1)*(EE/4) + e4] = crow1;
}

// Phase 2: 2 blocks per (b,h), 32 i-rows each; rv conv full (1024 FMA),
// ru conv over all 64 source rows in two 32-row passes (512 FMA total),
// correct global-j weight indexing in BOTH passes. One wave (512+16 blocks).
__global__ __launch_bounds__(256, 4) void k_convout(const float* __restrict__ w,
                                                    const float* __restrict__ o_,
                                                    float* __restrict__ out) {
    int blk = blockIdx.x;
    int t = threadIdx.x;

    if (blk < 512) {
        int bh = blk >> 1, half2 = blk & 1;
        int b = bh >> 4, h = bh & 15;
        int e4 = t & 15, kg = t >> 4;

        __shared__ float4 vs_s[SDIM*16];   // [j][e4]; becomes rv_s
        __shared__ float4 us_s[32*16];     // 32 source rows at a time
        __shared__ float4 ru_s[32*16];     // this block's 32 ru rows
        __shared__ float w_s[NW+1];

        const size_t base = (size_t)bh*SDIM*EE;
        const size_t slice4 = (size_t)BB*HH*SDIM*EE/4;
        {
            const float4* pa = reinterpret_cast<const float4*>(g_vs2 + base);
            #pragma unroll
            for (int r = 0; r < 4; ++r) {
                int idx = r*256 + t;
                float4 x = __ldg(pa + idx), y = __ldg(pa + slice4 + idx);
                vs_s[idx] = make_float4(x.x+y.x, x.y+y.y, x.z+y.z, x.w+y.w);
            }
            const float4* pu = reinterpret_cast<const float4*>(g_us + base);
            #pragma unroll
            for (int r = 0; r < 2; ++r) {
                int idx = r*256 + t;
                us_s[idx] = __ldg(pu + idx);      // source rows 0..31
            }
        }
        if (t < NW) w_s[t] = w[h*NW + t];
        if (t == NW) w_s[NW] = w[h*NW];
        __syncthreads();

        // rv conv: all 64 k
        float4 rv[4];
        #pragma unroll
        for (int kk = 0; kk < 4; ++kk) rv[kk] = make_float4(0.f,0.f,0.f,0.f);
        int k0 = kg*4;
        #pragma unroll
        for (int j = 0; j < SDIM; ++j) {
            float4 vs = vs_s[j*16 + e4];
            int idx0 = k0 + 64 - j;
            #pragma unroll
            for (int kk = 0; kk < 4; ++kk) {
                float wk = w_s[idx0 + kk];
                rv[kk].x += vs.x*wk; rv[kk].y += vs.y*wk;
                rv[kk].z += vs.z*wk; rv[kk].w += vs.w*wk;
            }
        }

        // ru conv pass 1: source rows 0..31 (global j = jl)
        float4 ru0 = make_float4(0.f,0.f,0.f,0.f), ru1 = ru0;
        int iglob = half2*32 + kg*2;
        #pragma unroll
        for (int jl = 0; jl < 32; ++jl) {
            float4 us = us_s[jl*16 + e4];
            float w0 = w_s[iglob     + 64 - jl];
            float w1 = w_s[iglob + 1 + 64 - jl];
            ru0.x += us.x*w0; ru0.y += us.y*w0; ru0.z += us.z*w0; ru0.w += us.w*w0;
            ru1.x += us.x*w1; ru1.y += us.y*w1; ru1.z += us.z*w1; ru1.w += us.w*w1;
        }
        __syncthreads();
        // ru conv pass 2: source rows 32..63
        {
            const float4* pu = reinterpret_cast<const float4*>(g_us + base) + 32*16;
            #pragma unroll
            for (int r = 0; r < 2; ++r) {
                int idx = r*256 + t;
                us_s[idx] = __ldg(pu + idx);
            }
        }
        __syncthreads();
        #pragma unroll
        for (int jl = 0; jl < 32; ++jl) {
            float4 us = us_s[jl*16 + e4];
            int jg = 32 + jl;
            float w0 = w_s[iglob     + 64 - jg];
            float w1 = w_s[iglob + 1 + 64 - jg];
            ru0.x += us.x*w0; ru0.y += us.y*w0; ru0.z += us.z*w0; ru0.w += us.w*w0;
            ru1.x += us.x*w1; ru1.y += us.y*w1; ru1.z += us.z*w1; ru1.w += us.w*w1;
        }
        ru_s[(kg*2    )*16 + e4] = ru0;
        ru_s[(kg*2 + 1)*16 + e4] = ru1;

        __syncthreads();
        #pragma unroll
        for (int kk = 0; kk < 4; ++kk)
            vs_s[(k0 + kk)*16 + e4] = rv[kk];
        __syncthreads();

        float4* out4 = reinterpret_cast<float4*>(out)
                     + (size_t)b*SS*(HH*EE/4) + h*(EE/4) + e4;
        #pragma unroll 1
        for (int ii = 0; ii < 32; ++ii) {
            int i = half2*32 + ii;
            float4 ruv = ru_s[ii*16 + e4];
            float4* orow = out4 + (size_t)(i*SDIM + kg*4)*(HH*EE/4);
            #pragma unroll
            for (int jj = 0; jj < 4; ++jj) {
                float4 rvv = vs_s[(kg*4 + jj)*16 + e4];
                float4 o;
                o.x = rvv.x + ruv.x; o.y = rvv.y + ruv.y;
                o.z = rvv.z + ruv.z; o.w = rvv.w + ruv.w;
                __stcs(orow + (size_t)jj*(HH*EE/4), o);
            }
        }
    } else {
        int zi = blk - 512;
        __shared__ float w_s2[HH*(NW+1)];
        __shared__ float o_s[SDIM];
        __shared__ float zc[HH*SDIM];

        for (int idx = t; idx < HH*NW; idx += 256) {
            int hh = idx / NW, kk = idx % NW;
            w_s2[hh*(NW+1) + kk] = w[idx];
        }
        if (t < HH) w_s2[t*(NW+1) + NW] = w[t*NW];
        if (t >= 32 && t < 32 + SDIM) o_s[t - 32] = o_[t - 32];
        __syncthreads();

        #pragma unroll
        for (int r = 0; r < 4; ++r) {
            int idx = r*256 + t;
            int hh = idx >> 6, k = idx & 63;
            float acc = 0.f;
            #pragma unroll
            for (int j = 0; j < SDIM; ++j)
                acc += o_s[j] * w_s2[hh*(NW+1) + (k + 64 - j)];
            zc[hh*SDIM + k] = acc * 64.f;
        }
        __syncthreads();

        float* o2 = out + (size_t)BB*SS*HH*EE;
        #pragma unroll
        for (int r = 0; r < 4; ++r) {
            int i = zi*4 + r;
            #pragma unroll
            for (int it = 0; it < 4; ++it) {
                int idx = it*256 + t;
                int j = idx >> 4, hh = idx & 15;
                o2[(size_t)i*1024 + idx] = zc[hh*SDIM + j] + zc[hh*SDIM + i];
            }
        }
    }
}

extern "C" void kernel_launch(void* const* d_in, const int* in_sizes, int n_in,
                              void* d_out, int out_size) {
    const float* v  = (const float*)d_in[0];
    const float* w  = (const float*)d_in[1];
    const float* o_ = (const float*)d_in[2];
    float* out = (float*)d_out;

    k_reduce <<<BB*HH*2, 256>>>(v);
    k_convout<<<512 + 16, 256>>>(w, o_, out);
}

// round 17
// speedup vs baseline: 1.0479x; 1.0479x over previous
#include <cuda_runtime.h>

#define BB 16
#define SS 4096
#define HH 16
#define EE 64
#define SDIM 64
#define NW 127

__device__ float g_vs2[2*BB*HH*SDIM*EE]; // [half][b][h][j][e] partial column sums
__device__ float g_us[BB*HH*SDIM*EE];    // [b][h][i][e]       row sums

// ---------------------------------------------------------------------------
// Kernel 1 (exact R5 config — measured 45-46us, ~75% DRAM): unchanged.
// ---------------------------------------------------------------------------
__global__ __launch_bounds__(256) void k_reduce(const float* __restrict__ v) {
    int bid = blockIdx.x;
    int bh = bid >> 1, half = bid & 1;
    int b = bh >> 4, h = bh & 15;
    int t = threadIdx.x;
    int e4 = t & 15, sub = (t >> 4) & 1, w = t >> 5;

    __shared__ float4 stage[2][8*8*16];   // 2 x 16KB

    const float4* v4 = reinterpret_cast<const float4*>(v)
                     + (size_t)b*SS*(HH*EE/4) + h*(EE/4) + e4;

    int i0 = half*32 + w*4 + sub*2;
    float4 crow0 = make_float4(0.f,0.f,0.f,0.f);
    float4 crow1 = make_float4(0.f,0.f,0.f,0.f);

    float* vs_dst = g_vs2 + (size_t)(half*BB*HH + bh)*SDIM*EE;

    #pragma unroll 1
    for (int jc = 0; jc < 8; ++jc) {
        float4 vloc[8];
        const float4* p0 = v4 + (size_t)(i0*SDIM + jc*8)*(HH*EE/4);
        const float4* p1 = p0 + (size_t)SDIM*(HH*EE/4);
        #pragma unroll
        for (int jj = 0; jj < 8; ++jj) {
            float4 a = __ldcs(p0 + (size_t)jj*(HH*EE/4));
            float4 c = __ldcs(p1 + (size_t)jj*(HH*EE/4));
            crow0.x += a.x; crow0.y += a.y; crow0.z += a.z; crow0.w += a.w;
            crow1.x += c.x; crow1.y += c.y; crow1.z += c.z; crow1.w += c.w;
            vloc[jj] = make_float4(a.x + c.x, a.y + c.y, a.z + c.z, a.w + c.w);
        }
        #pragma unroll
        for (int jj = 0; jj < 8; ++jj) {
            vloc[jj].x += __shfl_down_sync(0xffffffffu, vloc[jj].x, 16);
            vloc[jj].y += __shfl_down_sync(0xffffffffu, vloc[jj].y, 16);
            vloc[jj].z += __shfl_down_sync(0xffffffffu, vloc[jj].z, 16);
            vloc[jj].w += __shfl_down_sync(0xffffffffu, vloc[jj].w, 16);
        }
        if (sub == 0) {
            #pragma unroll
            for (int jj = 0; jj < 8; ++jj)
                stage[jc & 1][(w*8 + jj)*16 + e4] = vloc[jj];
        }
        __syncthreads();

        bool lower = (t < 128);
        if (lower == ((jc & 1) == 0)) {
            int tt = t & 127;
            int jj = tt >> 4, ee = tt & 15;
            float4 s = stage[jc & 1][jj*16 + ee];
            #pragma unroll
            for (int ww = 1; ww < 8; ++ww) {
                float4 x = stage[jc & 1][(ww*8 + jj)*16 + ee];
                s.x += x.x; s.y += x.y; s.z += x.z; s.w += x.w;
            }
            reinterpret_cast<float4*>(vs_dst + (jc*8 + jj)*EE)[ee] = s;
        }
    }

    float4* us4 = reinterpret_cast<float4*>(g_us + (size_t)bh*SDIM*EE);
    us4[(i0    )*(EE/4) + e4] = crow0;
    us4[(i0 + 1)*(EE/4) + e4] = crow1;
}

// ---------------------------------------------------------------------------
// Kernel 2 (R15 structure; smem unioned across branches; 5 blocks/SM):
// Blocks 0..1023: (bh, q). Load vs/us (48KB, L2-hot), conv rv at all 64 k
// (1024 FMA) + ru at only this quarter's 16 i (256 FMA), re-park in smem,
// stream 256KB of pbv with __stcs.
// Blocks 1024..1039: self-contained z_pb writers.
// ---------------------------------------------------------------------------
struct PhA { float4 vs[SDIM*16]; float4 us[SDIM*16];
             float4 ru[16*16]; float w[NW+1]; };         // ~36.6KB
struct PhZ { float w2[HH*(NW+1)]; float o[SDIM]; float zc[HH*SDIM]; };
union SMem2 { PhA a; PhZ z; };

__global__ __launch_bounds__(256, 5) void k_convout(const float* __restrict__ w,
                                                    const float* __restrict__ o_,
                                                    float* __restrict__ out) {
    __shared__ SMem2 sm;
    int blk = blockIdx.x;
    int t = threadIdx.x;

    if (blk < 1024) {
        int bh = blk >> 2, q = blk & 3;
        int b = bh >> 4, h = bh & 15;
        int e4 = t & 15, kg = t >> 4;

        const size_t base = (size_t)bh*SDIM*EE;
        const size_t slice4 = (size_t)BB*HH*SDIM*EE/4;
        {
            const float4* pa = reinterpret_cast<const float4*>(g_vs2 + base);
            const float4* pu = reinterpret_cast<const float4*>(g_us + base);
            #pragma unroll
            for (int r = 0; r < 4; ++r) {
                int idx = r*256 + t;
                float4 x = __ldg(pa + idx), y = __ldg(pa + slice4 + idx);
                sm.a.vs[idx] = make_float4(x.x+y.x, x.y+y.y, x.z+y.z, x.w+y.w);
                sm.a.us[idx] = __ldg(pu + idx);
            }
        }
        if (t < NW) sm.a.w[t] = w[h*NW + t];
        if (t == NW) sm.a.w[NW] = w[h*NW];   // pad: w[127] = w[0]
        __syncthreads();

        // rv conv: all 64 k; thread owns k = kg*4 + kk
        float4 rv[4];
        #pragma unroll
        for (int kk = 0; kk < 4; ++kk) rv[kk] = make_float4(0.f,0.f,0.f,0.f);
        int k0 = kg*4;
        #pragma unroll
        for (int j = 0; j < SDIM; ++j) {
            float4 vs = sm.a.vs[j*16 + e4];
            int idx0 = k0 + 64 - j;
            #pragma unroll
            for (int kk = 0; kk < 4; ++kk) {
                float wk = sm.a.w[idx0 + kk];
                rv[kk].x += vs.x*wk; rv[kk].y += vs.y*wk;
                rv[kk].z += vs.z*wk; rv[kk].w += vs.w*wk;
            }
        }

        // ru conv: only this quarter's 16 i-rows; thread owns i = q*16+kg
        {
            float4 ru = make_float4(0.f,0.f,0.f,0.f);
            int ii = q*16 + kg;
            #pragma unroll
            for (int j = 0; j < SDIM; ++j) {
                float4 us = sm.a.us[j*16 + e4];
                float wk = sm.a.w[ii + 64 - j];
                ru.x += us.x*wk; ru.y += us.y*wk;
                ru.z += us.z*wk; ru.w += us.w*wk;
            }
            sm.a.ru[kg*16 + e4] = ru;
        }

        __syncthreads();    // vs reads done; reuse for rv
        #pragma unroll
        for (int kk = 0; kk < 4; ++kk)
            sm.a.vs[(k0 + kk)*16 + e4] = rv[kk];
        __syncthreads();

        // write this quarter's 16 i-rows: out[b, i*64+j, h, e]
        float4* out4 = reinterpret_cast<float4*>(out)
                     + (size_t)b*SS*(HH*EE/4) + h*(EE/4) + e4;
        #pragma unroll 1
        for (int ii = 0; ii < 16; ++ii) {
            int i = q*16 + ii;
            float4 ruv = sm.a.ru[ii*16 + e4];
            float4* orow = out4 + (size_t)(i*SDIM + kg*4)*(HH*EE/4);
            #pragma unroll
            for (int jj = 0; jj < 4; ++jj) {
                float4 rvv = sm.a.vs[(kg*4 + jj)*16 + e4];
                float4 o;
                o.x = rvv.x + ruv.x; o.y = rvv.y + ruv.y;
                o.z = rvv.z + ruv.z; o.w = rvv.w + ruv.w;
                __stcs(orow + (size_t)jj*(HH*EE/4), o);
            }
        }
    } else {
        // ----- self-contained z_pb writers -----
        int zi = blk - 1024;
        for (int idx = t; idx < HH*NW; idx += 256) {
            int hh = idx / NW, kk = idx % NW;
            sm.z.w2[hh*(NW+1) + kk] = w[idx];
        }
        if (t < HH) sm.z.w2[t*(NW+1) + NW] = w[t*NW];
        if (t >= 32 && t < 32 + SDIM) sm.z.o[t - 32] = o_[t - 32];
        __syncthreads();

        #pragma unroll
        for (int r = 0; r < 4; ++r) {
            int idx = r*256 + t;             // h*64 + k
            int hh = idx >> 6, k = idx & 63;
            float acc = 0.f;
            #pragma unroll
            for (int j = 0; j < SDIM; ++j)
                acc += sm.z.o[j] * sm.z.w2[hh*(NW+1) + (k + 64 - j)];
            sm.z.zc[hh*SDIM + k] = acc * 64.f;
        }
        __syncthreads();

        float* o2 = out + (size_t)BB*SS*HH*EE;
        #pragma unroll
        for (int r = 0; r < 4; ++r) {
            int i = zi*4 + r;
            #pragma unroll
            for (int it = 0; it < 4; ++it) {
                int idx = it*256 + t;
                int j = idx >> 4, hh = idx & 15;
                o2[(size_t)i*1024 + idx] = sm.z.zc[hh*SDIM + j] + sm.z.zc[hh*SDIM + i];
            }
        }
    }
}

extern "C" void kernel_launch(void* const* d_in, const int* in_sizes, int n_in,
                              void* d_out, int out_size) {
    const float* v  = (const float*)d_in[0];
    const float* w  = (const float*)d_in[1];
    const float* o_ = (const float*)d_in[2];
    float* out = (float*)d_out;

    k_reduce <<<BB*HH*2, 256>>>(v);
    k_convout<<<1024 + 16, 256>>>(w, o_, out);
}